// round 1
// baseline (speedup 1.0000x reference)
#include <cuda_runtime.h>
#include <cuda_bf16.h>
#include <math.h>

// Problem constants
#define VOCAB 50000
#define HID   256
#define BATCH 512
#define G3H   768   // 3*HID

// GEMM tiling
#define BM 128
#define BN 64
#define BK 32
#define PAD 4
#define KSTR (BK + PAD)   // 36 floats -> 144B row stride (16B aligned)

// Scratch for gh = h0 @ w_hh^T  (512 x 768 fp32 = 1.5 MB) -- static, allocation-free
__device__ float g_gh[BATCH * G3H];

__device__ __forceinline__ unsigned f2tf32(float f) {
    unsigned u;
    asm("cvt.rna.tf32.f32 %0, %1;" : "=r"(u) : "f"(f));
    return u;
}

__device__ __forceinline__ void mma_tf32(float c[4],
                                         unsigned a0, unsigned a1, unsigned a2, unsigned a3,
                                         unsigned b0, unsigned b1) {
    asm volatile(
        "mma.sync.aligned.m16n8k8.row.col.f32.tf32.tf32.f32 "
        "{%0,%1,%2,%3}, {%4,%5,%6,%7}, {%8,%9}, {%0,%1,%2,%3};\n"
        : "+f"(c[0]), "+f"(c[1]), "+f"(c[2]), "+f"(c[3])
        : "r"(a0), "r"(a1), "r"(a2), "r"(a3), "r"(b0), "r"(b1));
}

// C[M,N] = A[M,K] @ B[N,K]^T  (both row-major), tf32 tensor cores, fp32 accum.
// TANH: C = tanh(acc + bias[n]); else C = acc.
// Requires: M % BM == 0, K % BK == 0, K % 4 == 0. N arbitrary (predicated).
// Block: 256 threads (8 warps: 4 along M x 2 along N). Warp tile 32x32.
template <bool TANH>
__global__ __launch_bounds__(256) void gemm_tf32_nt(
    const float* __restrict__ A, const float* __restrict__ B,
    const float* __restrict__ bias, float* __restrict__ C,
    int M, int N, int K)
{
    __shared__ unsigned As[BM * KSTR];
    __shared__ unsigned Bs[BN * KSTR];

    const int tid  = threadIdx.x;
    const int lane = tid & 31;
    const int warp = tid >> 5;
    const int wm   = warp & 3;   // 0..3 -> 32-row slab
    const int wn   = warp >> 2;  // 0..1 -> 32-col slab
    const int bm   = blockIdx.x * BM;   // x fastest => consecutive blocks share B tile (L2 reuse)
    const int bn   = blockIdx.y * BN;

    float acc[2][4][4];
#pragma unroll
    for (int mt = 0; mt < 2; mt++)
#pragma unroll
        for (int nt = 0; nt < 4; nt++)
#pragma unroll
            for (int i = 0; i < 4; i++) acc[mt][nt][i] = 0.0f;

    for (int k0 = 0; k0 < K; k0 += BK) {
        // ---- load A tile: BM x BK floats = 1024 float4, 4 per thread
#pragma unroll
        for (int i = 0; i < 4; i++) {
            int idx = tid + i * 256;
            int r  = idx >> 3;        // 0..127
            int c4 = idx & 7;         // 0..7
            float4 v = *(const float4*)(A + (size_t)(bm + r) * K + k0 + c4 * 4);
            uint4 t;
            t.x = f2tf32(v.x); t.y = f2tf32(v.y); t.z = f2tf32(v.z); t.w = f2tf32(v.w);
            *(uint4*)&As[r * KSTR + c4 * 4] = t;
        }
        // ---- load B tile: BN x BK floats = 512 float4, 2 per thread (predicated on N)
#pragma unroll
        for (int i = 0; i < 2; i++) {
            int idx = tid + i * 256;
            int r  = idx >> 3;        // 0..63
            int c4 = idx & 7;
            int n  = bn + r;
            float4 v = make_float4(0.f, 0.f, 0.f, 0.f);
            if (n < N) v = *(const float4*)(B + (size_t)n * K + k0 + c4 * 4);
            uint4 t;
            t.x = f2tf32(v.x); t.y = f2tf32(v.y); t.z = f2tf32(v.z); t.w = f2tf32(v.w);
            *(uint4*)&Bs[r * KSTR + c4 * 4] = t;
        }
        __syncthreads();

#pragma unroll
        for (int kk = 0; kk < BK; kk += 8) {
            unsigned a[2][4];
            unsigned b[4][2];
            const int kq = kk + (lane & 3);
#pragma unroll
            for (int mt = 0; mt < 2; mt++) {
                int row = wm * 32 + mt * 16 + (lane >> 2);
                a[mt][0] = As[row * KSTR + kq];
                a[mt][1] = As[(row + 8) * KSTR + kq];
                a[mt][2] = As[row * KSTR + kq + 4];
                a[mt][3] = As[(row + 8) * KSTR + kq + 4];
            }
#pragma unroll
            for (int nt = 0; nt < 4; nt++) {
                int col = wn * 32 + nt * 8 + (lane >> 2);
                b[nt][0] = Bs[col * KSTR + kq];
                b[nt][1] = Bs[col * KSTR + kq + 4];
            }
#pragma unroll
            for (int mt = 0; mt < 2; mt++)
#pragma unroll
                for (int nt = 0; nt < 4; nt++)
                    mma_tf32(acc[mt][nt], a[mt][0], a[mt][1], a[mt][2], a[mt][3],
                             b[nt][0], b[nt][1]);
        }
        __syncthreads();
    }

    // ---- epilogue
#pragma unroll
    for (int mt = 0; mt < 2; mt++) {
#pragma unroll
        for (int nt = 0; nt < 4; nt++) {
            int row0 = bm + wm * 32 + mt * 16 + (lane >> 2);
            int col0 = bn + wn * 32 + nt * 8 + 2 * (lane & 3);
#pragma unroll
            for (int i = 0; i < 4; i++) {
                int row = row0 + ((i >= 2) ? 8 : 0);
                int col = col0 + (i & 1);
                if (col < N) {
                    float v = acc[mt][nt][i];
                    if (TANH) v = tanhf(v + bias[col]);
                    C[(size_t)row * N + col] = v;
                }
            }
        }
    }
}

// GRU elementwise: gi = gather(w_ih col idx) + b_ih ; gh from scratch + b_hh
// h1 = (1-z)*n + z*h0
__global__ __launch_bounds__(HID) void gru_elem_kernel(
    const int* __restrict__ ids, const float* __restrict__ h0,
    const float* __restrict__ w_ih, const float* __restrict__ b_ih,
    const float* __restrict__ b_hh, const float* __restrict__ gh,
    float* __restrict__ h1)
{
    const int b = blockIdx.x;     // 0..511
    const int h = threadIdx.x;    // 0..255
    const int idx = ids[b];

    float gi_r = w_ih[(size_t)(0 * HID + h) * VOCAB + idx] + b_ih[0 * HID + h];
    float gi_z = w_ih[(size_t)(1 * HID + h) * VOCAB + idx] + b_ih[1 * HID + h];
    float gi_n = w_ih[(size_t)(2 * HID + h) * VOCAB + idx] + b_ih[2 * HID + h];

    const float* ghr = gh + (size_t)b * G3H;
    float gh_r = ghr[0 * HID + h] + b_hh[0 * HID + h];
    float gh_z = ghr[1 * HID + h] + b_hh[1 * HID + h];
    float gh_n = ghr[2 * HID + h] + b_hh[2 * HID + h];

    float r = 1.0f / (1.0f + __expf(-(gi_r + gh_r)));
    float z = 1.0f / (1.0f + __expf(-(gi_z + gh_z)));
    float n = tanhf(gi_n + r * gh_n);
    float hp = h0[(size_t)b * HID + h];
    h1[(size_t)b * HID + h] = (1.0f - z) * n + z * hp;
}

extern "C" void kernel_launch(void* const* d_in, const int* in_sizes, int n_in,
                              void* d_out, int out_size)
{
    const int*   ids    = (const int*)  d_in[0];
    const float* hidden = (const float*)d_in[1];   // [1, B, H]
    const float* w_ih   = (const float*)d_in[2];   // [3H, V]
    const float* w_hh   = (const float*)d_in[3];   // [3H, H]
    const float* b_ih   = (const float*)d_in[4];
    const float* b_hh   = (const float*)d_in[5];
    const float* w_out  = (const float*)d_in[6];   // [V, H]
    const float* b_out  = (const float*)d_in[7];

    float* out = (float*)d_out;                    // [B*V logits][B*H h1]
    float* h1  = out + ((size_t)out_size - (size_t)BATCH * HID);

    float* gh;
    cudaGetSymbolAddress((void**)&gh, g_gh);

    // 1) gh = hidden @ w_hh^T   (512 x 768, K=256), tf32 TC
    gemm_tf32_nt<false><<<dim3(BATCH / BM, G3H / BN), 256>>>(
        hidden, w_hh, nullptr, gh, BATCH, G3H, HID);

    // 2) GRU elementwise -> h1 (written into d_out tail)
    gru_elem_kernel<<<BATCH, HID>>>(ids, hidden, w_ih, b_ih, b_hh, gh, h1);

    // 3) logits = tanh(h1 @ w_out^T + b_out)   (512 x 50000, K=256), tf32 TC
    gemm_tf32_nt<true><<<dim3(BATCH / BM, (VOCAB + BN - 1) / BN), 256>>>(
        h1, w_out, b_out, out, BATCH, VOCAB, HID);
}

// round 3
// speedup vs baseline: 1.2459x; 1.2459x over previous
#include <cuda_runtime.h>
#include <cuda_fp16.h>
#include <cstdint>
#include <math.h>

#define VOCAB 50000
#define HID   256
#define BATCH 512
#define G3H   768

#define KDIM   256
#define BK     32
#define NSTAGE 8            // KDIM / BK
#define TMC    128          // CTA tile M
#define TNC    128          // CTA tile N
#define AST    40           // halves per smem row (32 + 8 pad) -> conflict-free frags

// scratch: gh = h0 @ w_hh^T  [512, 768] fp32
__device__ float g_gh[BATCH * G3H];

__device__ __forceinline__ float fast_tanh(float x) {
    x = fminf(fmaxf(x, -15.f), 15.f);
    float e = __expf(2.f * x);
    return __fdividef(e - 1.f, e + 1.f);
}

__device__ __forceinline__ void mma16816(float c[4], unsigned a0, unsigned a1,
                                         unsigned a2, unsigned a3,
                                         unsigned b0, unsigned b1) {
    asm volatile(
        "mma.sync.aligned.m16n8k16.row.col.f32.f16.f16.f32 "
        "{%0,%1,%2,%3}, {%4,%5,%6,%7}, {%8,%9}, {%0,%1,%2,%3};\n"
        : "+f"(c[0]), "+f"(c[1]), "+f"(c[2]), "+f"(c[3])
        : "r"(a0), "r"(a1), "r"(a2), "r"(a3), "r"(b0), "r"(b1));
}

// C[m,n] (row-major, ldC) = [tanh]( sum_k A[m,k]*B[n,k] [+ bias[n]] )
// A: [M,256] f32 row-major, M % 128 == 0 (grid.x = M/128)
// B: [N,256] f32 row-major, N predicated (grid.y = ceil(N/128))
// 512 threads = 16 warps (4 m x 4 n), warp tile 32x32, mma m16n8k16 fp16.
template <bool TANH>
__global__ __launch_bounds__(512) void gemm_h(
    const float* __restrict__ A, const float* __restrict__ B,
    const float* __restrict__ bias, float* __restrict__ C,
    int Ntot, int ldC)
{
    __shared__ __half As[2][TMC * AST];
    __shared__ __half Bs[2][TNC * AST];

    const int tid  = threadIdx.x;
    const int lane = tid & 31;
    const int warp = tid >> 5;
    const int wm   = warp & 3;       // 0..3
    const int wn   = warp >> 2;      // 0..3
    const int grp  = lane >> 2;      // 0..7
    const int kq   = lane & 3;       // 0..3
    const int m0   = blockIdx.x * TMC;
    const int n0   = blockIdx.y * TNC;

    float acc[2][4][4];
#pragma unroll
    for (int mt = 0; mt < 2; mt++)
#pragma unroll
        for (int nt = 0; nt < 4; nt++)
#pragma unroll
            for (int i = 0; i < 4; i++) acc[mt][nt][i] = 0.f;

    // per-thread fill coords: idx = tid + i*512, r = idx>>3, c4 = idx&7
    const int r0f = tid >> 3;          // rows 0..63 (i=0), 64..127 (i=1)
    const int c4  = tid & 7;

    float4 stA[2], stB[2];

    auto load_stage = [&](int s) {
        const int k0 = s * BK;
#pragma unroll
        for (int i = 0; i < 2; i++) {
            int r = r0f + i * 64;
            stA[i] = *(const float4*)(A + (size_t)(m0 + r) * KDIM + k0 + c4 * 4);
            int n = n0 + r;
            if (n < Ntot)
                stB[i] = *(const float4*)(B + (size_t)n * KDIM + k0 + c4 * 4);
            else
                stB[i] = make_float4(0.f, 0.f, 0.f, 0.f);
        }
    };
    auto store_stage = [&](int buf) {
#pragma unroll
        for (int i = 0; i < 2; i++) {
            int r = r0f + i * 64;
            __half2 a01 = __floats2half2_rn(stA[i].x, stA[i].y);
            __half2 a23 = __floats2half2_rn(stA[i].z, stA[i].w);
            *(__half2*)&As[buf][r * AST + c4 * 4]     = a01;
            *(__half2*)&As[buf][r * AST + c4 * 4 + 2] = a23;
            __half2 b01 = __floats2half2_rn(stB[i].x, stB[i].y);
            __half2 b23 = __floats2half2_rn(stB[i].z, stB[i].w);
            *(__half2*)&Bs[buf][r * AST + c4 * 4]     = b01;
            *(__half2*)&Bs[buf][r * AST + c4 * 4 + 2] = b23;
        }
    };

    // prologue
    load_stage(0);
    store_stage(0);
    __syncthreads();

    for (int s = 0; s < NSTAGE; s++) {
        const int buf = s & 1;
        if (s + 1 < NSTAGE) load_stage(s + 1);   // overlap LDG with mma below

        const unsigned* Ab = (const unsigned*)As[buf];
        const unsigned* Bb = (const unsigned*)Bs[buf];
#pragma unroll
        for (int kc = 0; kc < 2; kc++) {          // two k16 chunks in BK=32
            unsigned a[2][4], b[4][2];
#pragma unroll
            for (int mt = 0; mt < 2; mt++) {
                int ab = (wm * 32 + mt * 16 + grp) * (AST / 2) + kc * 8 + kq;
                a[mt][0] = Ab[ab];
                a[mt][1] = Ab[ab + 8 * (AST / 2)];
                a[mt][2] = Ab[ab + 4];
                a[mt][3] = Ab[ab + 8 * (AST / 2) + 4];
            }
#pragma unroll
            for (int nt = 0; nt < 4; nt++) {
                int bb = (wn * 32 + nt * 8 + grp) * (AST / 2) + kc * 8 + kq;
                b[nt][0] = Bb[bb];
                b[nt][1] = Bb[bb + 4];
            }
#pragma unroll
            for (int mt = 0; mt < 2; mt++)
#pragma unroll
                for (int nt = 0; nt < 4; nt++)
                    mma16816(acc[mt][nt], a[mt][0], a[mt][1], a[mt][2], a[mt][3],
                             b[nt][0], b[nt][1]);
        }

        if (s + 1 < NSTAGE) {
            store_stage((s + 1) & 1);
            __syncthreads();
        }
    }

    // epilogue: c0,c1 -> (row, col..col+1); c2,c3 -> (row+8, ...)
#pragma unroll
    for (int mt = 0; mt < 2; mt++) {
        int row = m0 + wm * 32 + mt * 16 + grp;
#pragma unroll
        for (int nt = 0; nt < 4; nt++) {
            int col = n0 + wn * 32 + nt * 8 + 2 * kq;
            if (col < Ntot) {   // Ntot even, col even -> col+1 also valid
                float bv0 = 0.f, bv1 = 0.f;
                if (TANH) { bv0 = bias[col]; bv1 = bias[col + 1]; }
                float2 v0, v1;
                v0.x = acc[mt][nt][0]; v0.y = acc[mt][nt][1];
                v1.x = acc[mt][nt][2]; v1.y = acc[mt][nt][3];
                if (TANH) {
                    v0.x = fast_tanh(v0.x + bv0); v0.y = fast_tanh(v0.y + bv1);
                    v1.x = fast_tanh(v1.x + bv0); v1.y = fast_tanh(v1.y + bv1);
                }
                *(float2*)(C + (size_t)row * ldC + col)       = v0;
                *(float2*)(C + (size_t)(row + 8) * ldC + col) = v1;
            }
        }
    }
}

// ---------- GRU elementwise ----------
__global__ __launch_bounds__(HID) void gru_elem_kernel(
    const int* __restrict__ ids, const float* __restrict__ h0,
    const float* __restrict__ w_ih, const float* __restrict__ b_ih,
    const float* __restrict__ b_hh, const float* __restrict__ gh,
    float* __restrict__ h1)
{
    const int b = blockIdx.x;
    const int h = threadIdx.x;
    const int idx = ids[b];

    float gi_r = w_ih[(size_t)(0 * HID + h) * VOCAB + idx] + b_ih[0 * HID + h];
    float gi_z = w_ih[(size_t)(1 * HID + h) * VOCAB + idx] + b_ih[1 * HID + h];
    float gi_n = w_ih[(size_t)(2 * HID + h) * VOCAB + idx] + b_ih[2 * HID + h];

    const float* ghr = gh + (size_t)b * G3H;
    float gh_r = ghr[0 * HID + h] + b_hh[0 * HID + h];
    float gh_z = ghr[1 * HID + h] + b_hh[1 * HID + h];
    float gh_n = ghr[2 * HID + h] + b_hh[2 * HID + h];

    float r = 1.0f / (1.0f + __expf(-(gi_r + gh_r)));
    float z = 1.0f / (1.0f + __expf(-(gi_z + gh_z)));
    float n = fast_tanh(gi_n + r * gh_n);
    float hp = h0[(size_t)b * HID + h];
    h1[(size_t)b * HID + h] = (1.0f - z) * n + z * hp;
}

extern "C" void kernel_launch(void* const* d_in, const int* in_sizes, int n_in,
                              void* d_out, int out_size)
{
    const int*   ids    = (const int*)  d_in[0];
    const float* hidden = (const float*)d_in[1];   // [1, B, H]
    const float* w_ih   = (const float*)d_in[2];   // [3H, V]
    const float* w_hh   = (const float*)d_in[3];   // [3H, H]
    const float* b_ih   = (const float*)d_in[4];
    const float* b_hh   = (const float*)d_in[5];
    const float* w_out  = (const float*)d_in[6];   // [V, H]
    const float* b_out  = (const float*)d_in[7];

    float* out = (float*)d_out;
    float* h1  = out + ((size_t)out_size - (size_t)BATCH * HID);

    float* gh;
    cudaGetSymbolAddress((void**)&gh, g_gh);

    // 1) gh = hidden @ w_hh^T : M=512 (batch), N=768
    gemm_h<false><<<dim3(BATCH / TMC, G3H / TNC), 512>>>(
        hidden, w_hh, nullptr, gh, G3H, G3H);

    // 2) GRU elementwise -> h1 (tail of d_out)
    gru_elem_kernel<<<BATCH, HID>>>(ids, hidden, w_ih, b_ih, b_hh, gh, h1);

    // 3) logits = tanh(h1 @ w_out^T + b_out) : M=512, N=50000
    gemm_h<true><<<dim3(BATCH / TMC, (VOCAB + TNC - 1) / TNC), 512>>>(
        h1, w_out, b_out, out, VOCAB, VOCAB);
}

// round 4
// speedup vs baseline: 1.7560x; 1.4095x over previous
#include <cuda_runtime.h>
#include <cuda_fp16.h>
#include <cstdint>
#include <math.h>

#define VOCAB 50000
#define HID   256
#define BATCH 512
#define G3H   768
#define KDIM  256
#define BK    32
#define NSTAGE (KDIM / BK)     // 8 k-stages
#define TM    128
#define TN    128
#define STAGE_A_BYTES (TM * 64)          // 128 rows x 32 halves
#define STAGE_B_BYTES (TN * 64)
#define STAGE_BYTES   (STAGE_A_BYTES + STAGE_B_BYTES)   // 16 KB
#define SMEM_BYTES    (4 * STAGE_BYTES)                 // 64 KB, 4-stage ring

// scratch (static device globals -- allocation-free)
__device__ float  g_gh[BATCH * G3H];                 // gh = h0 @ w_hh^T
__device__ __half g_woh[(size_t)VOCAB * HID];        // w_out fp16
__device__ __half g_whh[G3H * HID];                  // w_hh fp16
__device__ __half g_hidh[BATCH * HID];               // hidden fp16
__device__ __half g_h1h[BATCH * HID];                // h1 fp16

// ---------------- helpers ----------------
__device__ __forceinline__ uint32_t smem_u32(const void* p) {
    uint32_t a;
    asm("{ .reg .u64 t; cvta.to.shared.u64 t, %1; cvt.u32.u64 %0, t; }" : "=r"(a) : "l"(p));
    return a;
}
__device__ __forceinline__ void cp16(uint32_t d, const void* g) {
    asm volatile("cp.async.cg.shared.global [%0], [%1], 16;" :: "r"(d), "l"(g));
}
__device__ __forceinline__ void ldmA(uint32_t a[4], uint32_t addr) {
    asm volatile("ldmatrix.sync.aligned.m8n8.x4.shared.b16 {%0,%1,%2,%3}, [%4];"
                 : "=r"(a[0]), "=r"(a[1]), "=r"(a[2]), "=r"(a[3]) : "r"(addr));
}
__device__ __forceinline__ void ldmB(uint32_t b[2], uint32_t addr) {
    asm volatile("ldmatrix.sync.aligned.m8n8.x2.shared.b16 {%0,%1}, [%2];"
                 : "=r"(b[0]), "=r"(b[1]) : "r"(addr));
}
__device__ __forceinline__ void mma16816(float c[4], unsigned a0, unsigned a1,
                                         unsigned a2, unsigned a3,
                                         unsigned b0, unsigned b1) {
    asm volatile(
        "mma.sync.aligned.m16n8k16.row.col.f32.f16.f16.f32 "
        "{%0,%1,%2,%3}, {%4,%5,%6,%7}, {%8,%9}, {%0,%1,%2,%3};\n"
        : "+f"(c[0]), "+f"(c[1]), "+f"(c[2]), "+f"(c[3])
        : "r"(a0), "r"(a1), "r"(a2), "r"(a3), "r"(b0), "r"(b1));
}
__device__ __forceinline__ float fast_tanh(float x) {
    x = fminf(fmaxf(x, -15.f), 15.f);
    float e = __expf(2.f * x);
    return __fdividef(e - 1.f, e + 1.f);
}

// ---------------- f32 -> f16 conversion ----------------
__global__ __launch_bounds__(256) void convk(const float4* __restrict__ s,
                                             __half2* __restrict__ d, int n4) {
    int i = blockIdx.x * 256 + threadIdx.x;
    if (i < n4) {
        float4 v = s[i];
        d[2 * i]     = __floats2half2_rn(v.x, v.y);
        d[2 * i + 1] = __floats2half2_rn(v.z, v.w);
    }
}

// ---------------- fp16 tensor-core GEMM, cp.async 4-stage ----------------
// C[m,n] = [tanh]( sum_k A[m,k] * B[n,k] [+ bias[n]] )
// A: [512, 256] f16 row-major (M fixed 512, grid.x = 4)
// B: [Ntot, 256] f16 row-major, grid.y = ceil(Ntot/128); rows clamped.
// 256 threads = 8 warps (2 m x 4 n), warp tile 64x32, mma m16n8k16.
template <bool TANH>
__global__ __launch_bounds__(256, 2) void gemm16(
    const __half* __restrict__ A, const __half* __restrict__ B,
    const float* __restrict__ bias, float* __restrict__ C,
    int Ntot, int ldC)
{
    extern __shared__ char smem[];
    const int tid  = threadIdx.x;
    const int lane = tid & 31;
    const int warp = tid >> 5;
    const int wm   = warp & 1;        // 0..1 -> 64-row slab
    const int wn   = warp >> 1;       // 0..3 -> 32-col slab
    const int grp  = lane >> 2;
    const int kq   = lane & 3;
    const int m0   = blockIdx.x * TM;
    const int n0   = blockIdx.y * TN;
    const uint32_t sbase = smem_u32(smem);

    // cp.async mapping: 4 chunks of 16B per thread (2 A rows + 2 B rows)
    const int rA0 = tid >> 2;         // 0..63
    const int cc  = tid & 3;          // chunk-in-row

    // ldmatrix lane address components (swizzle const across mt/nt tiles)
    const int aRow  = wm * 64 + (lane & 15);
    const int aSw   = (aRow >> 1) & 3;
    const int aKsel = lane >> 4;              // 0/1 -> k-half
    const int bRow  = wn * 32 + (lane & 7);
    const int bSw   = (bRow >> 1) & 3;
    const int bKsel = (lane >> 3) & 1;

    float acc[4][4][4];
#pragma unroll
    for (int mt = 0; mt < 4; mt++)
#pragma unroll
        for (int nt = 0; nt < 4; nt++)
#pragma unroll
            for (int i = 0; i < 4; i++) acc[mt][nt][i] = 0.f;

    auto issue = [&](int s) {
        const int buf = s & 3;
        const uint32_t sA = sbase + buf * STAGE_BYTES;
        const uint32_t sB = sA + STAGE_A_BYTES;
        const int k0 = s * BK;
#pragma unroll
        for (int i = 0; i < 2; i++) {
            int r  = rA0 + i * 64;
            int sw = ((cc ^ ((r >> 1) & 3)) << 4);
            cp16(sA + r * 64 + sw, A + (size_t)(m0 + r) * KDIM + k0 + cc * 8);
            int rb = n0 + r;
            if (rb > Ntot - 1) rb = Ntot - 1;   // clamp; garbage cols masked in epilogue
            cp16(sB + r * 64 + sw, B + (size_t)rb * KDIM + k0 + cc * 8);
        }
        asm volatile("cp.async.commit_group;");
    };

    issue(0); issue(1); issue(2);

    for (int s = 0; s < NSTAGE; s++) {
        asm volatile("cp.async.wait_group %0;" :: "n"(2));
        __syncthreads();
        if (s + 3 < NSTAGE) issue(s + 3);
        else asm volatile("cp.async.commit_group;");   // keep group accounting

        const int buf = s & 3;
        const uint32_t sA = sbase + buf * STAGE_BYTES;
        const uint32_t sB = sA + STAGE_A_BYTES;

#pragma unroll
        for (int kc = 0; kc < 2; kc++) {
            uint32_t a[4][4], b[4][2];
#pragma unroll
            for (int mt = 0; mt < 4; mt++)
                ldmA(a[mt], sA + (aRow + mt * 16) * 64 + (((2 * kc + aKsel) ^ aSw) << 4));
#pragma unroll
            for (int nt = 0; nt < 4; nt++)
                ldmB(b[nt], sB + (bRow + nt * 8) * 64 + (((2 * kc + bKsel) ^ bSw) << 4));
#pragma unroll
            for (int mt = 0; mt < 4; mt++)
#pragma unroll
                for (int nt = 0; nt < 4; nt++)
                    mma16816(acc[mt][nt], a[mt][0], a[mt][1], a[mt][2], a[mt][3],
                             b[nt][0], b[nt][1]);
        }
        // next iteration's top syncthreads guards buffer reuse
    }

    // epilogue
#pragma unroll
    for (int mt = 0; mt < 4; mt++) {
        int row = m0 + wm * 64 + mt * 16 + grp;
#pragma unroll
        for (int nt = 0; nt < 4; nt++) {
            int col = n0 + wn * 32 + nt * 8 + 2 * kq;
            if (col < Ntot) {
                float bv0 = 0.f, bv1 = 0.f;
                if (TANH) { bv0 = bias[col]; bv1 = bias[col + 1]; }
                float2 v0, v1;
                v0.x = acc[mt][nt][0]; v0.y = acc[mt][nt][1];
                v1.x = acc[mt][nt][2]; v1.y = acc[mt][nt][3];
                if (TANH) {
                    v0.x = fast_tanh(v0.x + bv0); v0.y = fast_tanh(v0.y + bv1);
                    v1.x = fast_tanh(v1.x + bv0); v1.y = fast_tanh(v1.y + bv1);
                }
                *(float2*)(C + (size_t)row * ldC + col)       = v0;
                *(float2*)(C + (size_t)(row + 8) * ldC + col) = v1;
            }
        }
    }
}

// ---------------- GRU elementwise ----------------
__global__ __launch_bounds__(HID) void gru_elem_kernel(
    const int* __restrict__ ids, const float* __restrict__ h0,
    const float* __restrict__ w_ih, const float* __restrict__ b_ih,
    const float* __restrict__ b_hh, const float* __restrict__ gh,
    float* __restrict__ h1, __half* __restrict__ h1h)
{
    const int b = blockIdx.x;
    const int h = threadIdx.x;
    const int idx = ids[b];

    float gi_r = w_ih[(size_t)(0 * HID + h) * VOCAB + idx] + b_ih[0 * HID + h];
    float gi_z = w_ih[(size_t)(1 * HID + h) * VOCAB + idx] + b_ih[1 * HID + h];
    float gi_n = w_ih[(size_t)(2 * HID + h) * VOCAB + idx] + b_ih[2 * HID + h];

    const float* ghr = gh + (size_t)b * G3H;
    float gh_r = ghr[0 * HID + h] + b_hh[0 * HID + h];
    float gh_z = ghr[1 * HID + h] + b_hh[1 * HID + h];
    float gh_n = ghr[2 * HID + h] + b_hh[2 * HID + h];

    float r = 1.0f / (1.0f + __expf(-(gi_r + gh_r)));
    float z = 1.0f / (1.0f + __expf(-(gi_z + gh_z)));
    float n = fast_tanh(gi_n + r * gh_n);
    float hp = h0[(size_t)b * HID + h];
    float hv = (1.0f - z) * n + z * hp;
    h1[(size_t)b * HID + h]  = hv;
    h1h[(size_t)b * HID + h] = __float2half(hv);
}

extern "C" void kernel_launch(void* const* d_in, const int* in_sizes, int n_in,
                              void* d_out, int out_size)
{
    const int*   ids    = (const int*)  d_in[0];
    const float* hidden = (const float*)d_in[1];   // [1, B, H]
    const float* w_ih   = (const float*)d_in[2];   // [3H, V]
    const float* w_hh   = (const float*)d_in[3];   // [3H, H]
    const float* b_ih   = (const float*)d_in[4];
    const float* b_hh   = (const float*)d_in[5];
    const float* w_out  = (const float*)d_in[6];   // [V, H]
    const float* b_out  = (const float*)d_in[7];

    float* out = (float*)d_out;
    float* h1  = out + ((size_t)out_size - (size_t)BATCH * HID);

    float* gh;   cudaGetSymbolAddress((void**)&gh,  g_gh);
    __half* woh; cudaGetSymbolAddress((void**)&woh, g_woh);
    __half* whh; cudaGetSymbolAddress((void**)&whh, g_whh);
    __half* hih; cudaGetSymbolAddress((void**)&hih, g_hidh);
    __half* h1h; cudaGetSymbolAddress((void**)&h1h, g_h1h);

    static bool attr_done = false;
    if (!attr_done) {
        cudaFuncSetAttribute(gemm16<false>, cudaFuncAttributeMaxDynamicSharedMemorySize, SMEM_BYTES);
        cudaFuncSetAttribute(gemm16<true>,  cudaFuncAttributeMaxDynamicSharedMemorySize, SMEM_BYTES);
        attr_done = true;
    }

    // conversions to fp16
    {
        int n4 = (VOCAB * HID) / 4;            // 3.2M
        convk<<<(n4 + 255) / 256, 256>>>((const float4*)w_out, (__half2*)woh, n4);
    }
    {
        int n4 = (G3H * HID) / 4;
        convk<<<(n4 + 255) / 256, 256>>>((const float4*)w_hh, (__half2*)whh, n4);
    }
    {
        int n4 = (BATCH * HID) / 4;
        convk<<<(n4 + 255) / 256, 256>>>((const float4*)hidden, (__half2*)hih, n4);
    }

    // 1) gh = hidden @ w_hh^T : M=512, N=768
    gemm16<false><<<dim3(BATCH / TM, G3H / TN), 256, SMEM_BYTES>>>(
        hih, whh, nullptr, gh, G3H, G3H);

    // 2) GRU elementwise -> h1 (f32 into d_out tail, f16 scratch)
    gru_elem_kernel<<<BATCH, HID>>>(ids, hidden, w_ih, b_ih, b_hh, gh, h1, h1h);

    // 3) logits = tanh(h1 @ w_out^T + b_out) : M=512, N=50000
    gemm16<true><<<dim3(BATCH / TM, (VOCAB + TN - 1) / TN), 256, SMEM_BYTES>>>(
        h1h, woh, b_out, out, VOCAB, VOCAB);
}

// round 5
// speedup vs baseline: 1.8137x; 1.0329x over previous
#include <cuda_runtime.h>
#include <cuda_fp16.h>
#include <cstdint>
#include <math.h>

#define VOCAB 50000
#define HID   256
#define BATCH 512
#define G3H   768
#define KDIM  256
#define BK    64
#define KSTAGES (KDIM / BK)          // 4
#define TM    128
#define TN    128
#define STAGE_A (TM * BK * 2)        // 16 KB
#define STAGE_B (TN * BK * 2)        // 16 KB
#define STAGE_BYTES (STAGE_A + STAGE_B)   // 32 KB
#define RING  3
#define SMEM_BYTES (RING * STAGE_BYTES)   // 96 KB

// scratch (static device globals -- allocation-free)
__device__ float  g_gh[BATCH * G3H];
__device__ __half g_woh[(size_t)VOCAB * HID];
__device__ __half g_whh[G3H * HID];
__device__ __half g_hidh[BATCH * HID];
__device__ __half g_h1h[BATCH * HID];

// ---------------- helpers ----------------
__device__ __forceinline__ uint32_t smem_u32(const void* p) {
    uint32_t a;
    asm("{ .reg .u64 t; cvta.to.shared.u64 t, %1; cvt.u32.u64 %0, t; }" : "=r"(a) : "l"(p));
    return a;
}
__device__ __forceinline__ void cp16(uint32_t d, const void* g) {
    asm volatile("cp.async.cg.shared.global [%0], [%1], 16;" :: "r"(d), "l"(g));
}
__device__ __forceinline__ void ldmA(uint32_t a[4], uint32_t addr) {
    asm volatile("ldmatrix.sync.aligned.m8n8.x4.shared.b16 {%0,%1,%2,%3}, [%4];"
                 : "=r"(a[0]), "=r"(a[1]), "=r"(a[2]), "=r"(a[3]) : "r"(addr));
}
__device__ __forceinline__ void ldmB(uint32_t b[2], uint32_t addr) {
    asm volatile("ldmatrix.sync.aligned.m8n8.x2.shared.b16 {%0,%1}, [%2];"
                 : "=r"(b[0]), "=r"(b[1]) : "r"(addr));
}
__device__ __forceinline__ void mma16816(float c[4], unsigned a0, unsigned a1,
                                         unsigned a2, unsigned a3,
                                         unsigned b0, unsigned b1) {
    asm volatile(
        "mma.sync.aligned.m16n8k16.row.col.f32.f16.f16.f32 "
        "{%0,%1,%2,%3}, {%4,%5,%6,%7}, {%8,%9}, {%0,%1,%2,%3};\n"
        : "+f"(c[0]), "+f"(c[1]), "+f"(c[2]), "+f"(c[3])
        : "r"(a0), "r"(a1), "r"(a2), "r"(a3), "r"(b0), "r"(b1));
}
__device__ __forceinline__ float fast_tanh(float x) {
    x = fminf(fmaxf(x, -15.f), 15.f);
    float e = __expf(2.f * x);
    return __fdividef(e - 1.f, e + 1.f);
}

// ---------------- conversions ----------------
__global__ __launch_bounds__(256) void convk(const float4* __restrict__ s,
                                             __half2* __restrict__ d, int n4) {
    int i = blockIdx.x * 256 + threadIdx.x;
    if (i < n4) {
        float4 v = s[i];
        d[2 * i]     = __floats2half2_rn(v.x, v.y);
        d[2 * i + 1] = __floats2half2_rn(v.z, v.w);
    }
}
__global__ __launch_bounds__(256) void convall(
    const float4* __restrict__ s1, __half2* __restrict__ d1, int n1,
    const float4* __restrict__ s2, __half2* __restrict__ d2, int n2)
{
    int i = blockIdx.x * 256 + threadIdx.x;
    if (i < n1) {
        float4 v = s1[i];
        d1[2 * i]     = __floats2half2_rn(v.x, v.y);
        d1[2 * i + 1] = __floats2half2_rn(v.z, v.w);
    } else {
        int j = i - n1;
        if (j < n2) {
            float4 v = s2[j];
            d2[2 * j]     = __floats2half2_rn(v.x, v.y);
            d2[2 * j + 1] = __floats2half2_rn(v.z, v.w);
        }
    }
}

// ---------------- fp16 GEMM: BK=64, 3-stage cp.async ring, frag double-buffer ----
// C[m,n] = [tanh]( sum_k A[m,k]*B[n,k] [+ bias[n]] )
// A: [M,256] f16 row-major, M % 128 == 0.  B: [Ntot,256] f16, rows clamped.
// 256 threads = 8 warps (2m x 4n), warp tile 64x32, mma m16n8k16.
template <bool TANH>
__global__ __launch_bounds__(256, 2) void gemm16(
    const __half* __restrict__ A, const __half* __restrict__ B,
    const float* __restrict__ bias, float* __restrict__ C,
    int Ntot, int ldC)
{
    extern __shared__ char smem[];
    const int tid  = threadIdx.x;
    const int lane = tid & 31;
    const int warp = tid >> 5;
    const int wm   = warp & 1;
    const int wn   = warp >> 1;
    const int grp  = lane >> 2;
    const int kq   = lane & 3;
    const int m0   = blockIdx.x * TM;
    const int n0   = blockIdx.y * TN;
    const uint32_t sbase = smem_u32(smem);

    // cp.async mapping: full 128B rows, 8 chunks of 16B; 256 thr -> 32 rows/pass
    const int rcp = tid >> 3;        // 0..31
    const int cc  = tid & 7;         // chunk in row

    // ldmatrix lane addressing
    const int aRow = wm * 64 + (lane & 15);
    const int aSwz = aRow & 7;
    const int aK   = lane >> 4;                 // 0/1
    const int bRow = wn * 32 + (lane & 7);
    const int bSwz = bRow & 7;
    const int bK   = (lane >> 3) & 1;

    float acc[4][4][4];
#pragma unroll
    for (int mt = 0; mt < 4; mt++)
#pragma unroll
        for (int nt = 0; nt < 4; nt++)
#pragma unroll
            for (int i = 0; i < 4; i++) acc[mt][nt][i] = 0.f;

    auto issue = [&](int s) {
        if (s < KSTAGES) {
            const uint32_t sA = sbase + (s % RING) * STAGE_BYTES;
            const uint32_t sB = sA + STAGE_A;
            const int k0 = s * BK;
#pragma unroll
            for (int i = 0; i < 4; i++) {
                int row = rcp + 32 * i;
                uint32_t dst = row * 128 + ((cc ^ (row & 7)) << 4);
                cp16(sA + dst, A + (size_t)(m0 + row) * KDIM + k0 + cc * 8);
                int rb = n0 + row;
                if (rb > Ntot - 1) rb = Ntot - 1;
                cp16(sB + dst, B + (size_t)rb * KDIM + k0 + cc * 8);
            }
        }
        asm volatile("cp.async.commit_group;");
    };

#define LD_FRAGS(aF, bF, kc) do {                                              \
    _Pragma("unroll")                                                          \
    for (int mt = 0; mt < 4; mt++)                                             \
        ldmA(aF[mt], sA + (uint32_t)((aRow + mt * 16) * 128)                   \
                        + ((((2 * (kc)) + aK) ^ aSwz) << 4));                  \
    _Pragma("unroll")                                                          \
    for (int nt = 0; nt < 4; nt++)                                             \
        ldmB(bF[nt], sB + (uint32_t)((bRow + nt * 8) * 128)                    \
                        + ((((2 * (kc)) + bK) ^ bSwz) << 4));                  \
} while (0)

#define MMA_BLOCK(aF, bF) do {                                                 \
    _Pragma("unroll")                                                          \
    for (int mt = 0; mt < 4; mt++)                                             \
        _Pragma("unroll")                                                      \
        for (int nt = 0; nt < 4; nt++)                                         \
            mma16816(acc[mt][nt], aF[mt][0], aF[mt][1], aF[mt][2], aF[mt][3],  \
                     bF[nt][0], bF[nt][1]);                                    \
} while (0)

    issue(0); issue(1); issue(2);

    uint32_t a0[4][4], b0[4][2], a1[4][4], b1[4][2];

#pragma unroll
    for (int s = 0; s < KSTAGES; s++) {
        asm volatile("cp.async.wait_group %0;" :: "n"(2));
        __syncthreads();
        const uint32_t sA = sbase + (s % RING) * STAGE_BYTES;
        const uint32_t sB = sA + STAGE_A;

        LD_FRAGS(a0, b0, 0);
        LD_FRAGS(a1, b1, 1);
        MMA_BLOCK(a0, b0);          // kc0
        LD_FRAGS(a0, b0, 2);
        MMA_BLOCK(a1, b1);          // kc1
        LD_FRAGS(a1, b1, 3);
        __syncthreads();            // all smem reads of stage s done
        issue(s + 3);               // refill this ring slot
        MMA_BLOCK(a0, b0);          // kc2
        MMA_BLOCK(a1, b1);          // kc3
    }

    // epilogue
#pragma unroll
    for (int mt = 0; mt < 4; mt++) {
        int row = m0 + wm * 64 + mt * 16 + grp;
#pragma unroll
        for (int nt = 0; nt < 4; nt++) {
            int col = n0 + wn * 32 + nt * 8 + 2 * kq;
            if (col < Ntot) {
                float bv0 = 0.f, bv1 = 0.f;
                if (TANH) { bv0 = bias[col]; bv1 = bias[col + 1]; }
                float2 v0, v1;
                v0.x = acc[mt][nt][0]; v0.y = acc[mt][nt][1];
                v1.x = acc[mt][nt][2]; v1.y = acc[mt][nt][3];
                if (TANH) {
                    v0.x = fast_tanh(v0.x + bv0); v0.y = fast_tanh(v0.y + bv1);
                    v1.x = fast_tanh(v1.x + bv0); v1.y = fast_tanh(v1.y + bv1);
                }
                *(float2*)(C + (size_t)row * ldC + col)       = v0;
                *(float2*)(C + (size_t)(row + 8) * ldC + col) = v1;
            }
        }
    }
#undef LD_FRAGS
#undef MMA_BLOCK
}

// ---------------- GRU elementwise ----------------
__global__ __launch_bounds__(HID) void gru_elem_kernel(
    const int* __restrict__ ids, const float* __restrict__ h0,
    const float* __restrict__ w_ih, const float* __restrict__ b_ih,
    const float* __restrict__ b_hh, const float* __restrict__ gh,
    float* __restrict__ h1, __half* __restrict__ h1h)
{
    const int b = blockIdx.x;
    const int h = threadIdx.x;
    const int idx = ids[b];

    float gi_r = w_ih[(size_t)(0 * HID + h) * VOCAB + idx] + b_ih[0 * HID + h];
    float gi_z = w_ih[(size_t)(1 * HID + h) * VOCAB + idx] + b_ih[1 * HID + h];
    float gi_n = w_ih[(size_t)(2 * HID + h) * VOCAB + idx] + b_ih[2 * HID + h];

    const float* ghr = gh + (size_t)b * G3H;
    float gh_r = ghr[0 * HID + h] + b_hh[0 * HID + h];
    float gh_z = ghr[1 * HID + h] + b_hh[1 * HID + h];
    float gh_n = ghr[2 * HID + h] + b_hh[2 * HID + h];

    float r = 1.0f / (1.0f + __expf(-(gi_r + gh_r)));
    float z = 1.0f / (1.0f + __expf(-(gi_z + gh_z)));
    float n = fast_tanh(gi_n + r * gh_n);
    float hp = h0[(size_t)b * HID + h];
    float hv = (1.0f - z) * n + z * hp;
    h1[(size_t)b * HID + h]  = hv;
    h1h[(size_t)b * HID + h] = __float2half(hv);
}

extern "C" void kernel_launch(void* const* d_in, const int* in_sizes, int n_in,
                              void* d_out, int out_size)
{
    const int*   ids    = (const int*)  d_in[0];
    const float* hidden = (const float*)d_in[1];
    const float* w_ih   = (const float*)d_in[2];
    const float* w_hh   = (const float*)d_in[3];
    const float* b_ih   = (const float*)d_in[4];
    const float* b_hh   = (const float*)d_in[5];
    const float* w_out  = (const float*)d_in[6];
    const float* b_out  = (const float*)d_in[7];

    float* out = (float*)d_out;
    float* h1  = out + ((size_t)out_size - (size_t)BATCH * HID);

    float* gh;   cudaGetSymbolAddress((void**)&gh,  g_gh);
    __half* woh; cudaGetSymbolAddress((void**)&woh, g_woh);
    __half* whh; cudaGetSymbolAddress((void**)&whh, g_whh);
    __half* hih; cudaGetSymbolAddress((void**)&hih, g_hidh);
    __half* h1h; cudaGetSymbolAddress((void**)&h1h, g_h1h);

    static cudaStream_t s2 = nullptr;
    static cudaEvent_t ev0 = nullptr, ev1 = nullptr;
    if (!s2) {
        cudaFuncSetAttribute(gemm16<false>, cudaFuncAttributeMaxDynamicSharedMemorySize, SMEM_BYTES);
        cudaFuncSetAttribute(gemm16<true>,  cudaFuncAttributeMaxDynamicSharedMemorySize, SMEM_BYTES);
        cudaStreamCreateWithFlags(&s2, cudaStreamNonBlocking);
        cudaEventCreateWithFlags(&ev0, cudaEventDisableTiming);
        cudaEventCreateWithFlags(&ev1, cudaEventDisableTiming);
    }

    // ---- fork: w_out conversion on side stream (overlaps K1 chain) ----
    cudaEventRecord(ev0, (cudaStream_t)0);
    cudaStreamWaitEvent(s2, ev0, 0);
    {
        int n4 = (VOCAB * HID) / 4;
        convk<<<(n4 + 255) / 256, 256, 0, s2>>>((const float4*)w_out, (__half2*)woh, n4);
    }
    cudaEventRecord(ev1, s2);

    // ---- main stream: small convs, K1, gru ----
    {
        int n1 = (G3H * HID) / 4, n2 = (BATCH * HID) / 4;
        convall<<<(n1 + n2 + 255) / 256, 256>>>(
            (const float4*)w_hh, (__half2*)whh, n1,
            (const float4*)hidden, (__half2*)hih, n2);
    }
    gemm16<false><<<dim3(BATCH / TM, G3H / TN), 256, SMEM_BYTES>>>(
        hih, whh, nullptr, gh, G3H, G3H);
    gru_elem_kernel<<<BATCH, HID>>>(ids, hidden, w_ih, b_ih, b_hh, gh, h1, h1h);

    // ---- join, then the big GEMM ----
    cudaStreamWaitEvent((cudaStream_t)0, ev1, 0);
    gemm16<true><<<dim3(BATCH / TM, (VOCAB + TN - 1) / TN), 256, SMEM_BYTES>>>(
        h1h, woh, b_out, out, VOCAB, VOCAB);
}

// round 6
// speedup vs baseline: 1.8401x; 1.0145x over previous
#include <cuda_runtime.h>
#include <cuda_fp16.h>
#include <cstdint>
#include <math.h>

#define VOCAB 50000
#define HID   256
#define BATCH 512
#define G3H   768
#define KDIM  256
#define BK    32
#define NSTAGE (KDIM / BK)     // 8 k-stages
#define TM    128
#define TN    128
#define STAGE_A_BYTES (TM * 64)
#define STAGE_B_BYTES (TN * 64)
#define STAGE_BYTES   (STAGE_A_BYTES + STAGE_B_BYTES)   // 16 KB
#define SMEM_BYTES    (4 * STAGE_BYTES)                 // 64 KB, 4-stage ring

// scratch (static device globals -- allocation-free)
__device__ float  g_gh[BATCH * G3H];
__device__ float  g_gi[BATCH * G3H];
__device__ __half g_woh[(size_t)VOCAB * HID];
__device__ __half g_whh[G3H * HID];
__device__ __half g_hidh[BATCH * HID];
__device__ __half g_h1h[BATCH * HID];

// ---------------- helpers ----------------
__device__ __forceinline__ uint32_t smem_u32(const void* p) {
    uint32_t a;
    asm("{ .reg .u64 t; cvta.to.shared.u64 t, %1; cvt.u32.u64 %0, t; }" : "=r"(a) : "l"(p));
    return a;
}
__device__ __forceinline__ void cp16(uint32_t d, const void* g) {
    asm volatile("cp.async.cg.shared.global [%0], [%1], 16;" :: "r"(d), "l"(g));
}
__device__ __forceinline__ void ldmA(uint32_t a[4], uint32_t addr) {
    asm volatile("ldmatrix.sync.aligned.m8n8.x4.shared.b16 {%0,%1,%2,%3}, [%4];"
                 : "=r"(a[0]), "=r"(a[1]), "=r"(a[2]), "=r"(a[3]) : "r"(addr));
}
__device__ __forceinline__ void ldmB(uint32_t b[2], uint32_t addr) {
    asm volatile("ldmatrix.sync.aligned.m8n8.x2.shared.b16 {%0,%1}, [%2];"
                 : "=r"(b[0]), "=r"(b[1]) : "r"(addr));
}
__device__ __forceinline__ void mma16816(float c[4], unsigned a0, unsigned a1,
                                         unsigned a2, unsigned a3,
                                         unsigned b0, unsigned b1) {
    asm volatile(
        "mma.sync.aligned.m16n8k16.row.col.f32.f16.f16.f32 "
        "{%0,%1,%2,%3}, {%4,%5,%6,%7}, {%8,%9}, {%0,%1,%2,%3};\n"
        : "+f"(c[0]), "+f"(c[1]), "+f"(c[2]), "+f"(c[3])
        : "r"(a0), "r"(a1), "r"(a2), "r"(a3), "r"(b0), "r"(b1));
}
__device__ __forceinline__ float fast_tanh(float x) {
    x = fminf(fmaxf(x, -15.f), 15.f);
    float e = __expf(2.f * x);
    return __fdividef(e - 1.f, e + 1.f);
}

// ---------------- conversions ----------------
__global__ __launch_bounds__(256) void convk(const float4* __restrict__ s,
                                             __half2* __restrict__ d, int n4) {
    int i = blockIdx.x * 256 + threadIdx.x;
    if (i < n4) {
        float4 v = s[i];
        d[2 * i]     = __floats2half2_rn(v.x, v.y);
        d[2 * i + 1] = __floats2half2_rn(v.z, v.w);
    }
}
__global__ __launch_bounds__(256) void convall(
    const float4* __restrict__ s1, __half2* __restrict__ d1, int n1,
    const float4* __restrict__ s2, __half2* __restrict__ d2, int n2)
{
    int i = blockIdx.x * 256 + threadIdx.x;
    if (i < n1) {
        float4 v = s1[i];
        d1[2 * i]     = __floats2half2_rn(v.x, v.y);
        d1[2 * i + 1] = __floats2half2_rn(v.z, v.w);
    } else {
        int j = i - n1;
        if (j < n2) {
            float4 v = s2[j];
            d2[2 * j]     = __floats2half2_rn(v.x, v.y);
            d2[2 * j + 1] = __floats2half2_rn(v.z, v.w);
        }
    }
}

// ---------------- w_ih gather: one 4B load per thread, max MLP ----------------
// gi[b, h] = w_ih[h, ids[b]] + b_ih[h]   (h in [0, 768))
__global__ __launch_bounds__(256) void gather_gi(
    const int* __restrict__ ids, const float* __restrict__ w_ih,
    const float* __restrict__ b_ih, float* __restrict__ gi)
{
    const int h = blockIdx.x * 256 + threadIdx.x;   // 0..767 (grid.x = 3)
    const int b = blockIdx.y;                       // 0..511
    const int idx = __ldg(&ids[b]);
    gi[b * G3H + h] = __ldg(&w_ih[(size_t)h * VOCAB + idx]) + b_ih[h];
}

// ---------------- fp16 GEMM (R4 structure: BK=32, 4-stage cp.async) ----------
template <bool TANH>
__global__ __launch_bounds__(256, 2) void gemm16(
    const __half* __restrict__ A, const __half* __restrict__ B,
    const float* __restrict__ bias, float* __restrict__ C,
    int Ntot, int ldC)
{
    extern __shared__ char smem[];
    const int tid  = threadIdx.x;
    const int lane = tid & 31;
    const int warp = tid >> 5;
    const int wm   = warp & 1;
    const int wn   = warp >> 1;
    const int grp  = lane >> 2;
    const int kq   = lane & 3;
    const int m0   = blockIdx.x * TM;
    const int n0   = blockIdx.y * TN;
    const uint32_t sbase = smem_u32(smem);

    const int rA0 = tid >> 2;
    const int cc  = tid & 3;

    const int aRow  = wm * 64 + (lane & 15);
    const int aSw   = (aRow >> 1) & 3;
    const int aKsel = lane >> 4;
    const int bRow  = wn * 32 + (lane & 7);
    const int bSw   = (bRow >> 1) & 3;
    const int bKsel = (lane >> 3) & 1;

    float acc[4][4][4];
#pragma unroll
    for (int mt = 0; mt < 4; mt++)
#pragma unroll
        for (int nt = 0; nt < 4; nt++)
#pragma unroll
            for (int i = 0; i < 4; i++) acc[mt][nt][i] = 0.f;

    auto issue = [&](int s) {
        const int buf = s & 3;
        const uint32_t sA = sbase + buf * STAGE_BYTES;
        const uint32_t sB = sA + STAGE_A_BYTES;
        const int k0 = s * BK;
#pragma unroll
        for (int i = 0; i < 2; i++) {
            int r  = rA0 + i * 64;
            int sw = ((cc ^ ((r >> 1) & 3)) << 4);
            cp16(sA + r * 64 + sw, A + (size_t)(m0 + r) * KDIM + k0 + cc * 8);
            int rb = n0 + r;
            if (rb > Ntot - 1) rb = Ntot - 1;
            cp16(sB + r * 64 + sw, B + (size_t)rb * KDIM + k0 + cc * 8);
        }
        asm volatile("cp.async.commit_group;");
    };

    issue(0); issue(1); issue(2);

    for (int s = 0; s < NSTAGE; s++) {
        asm volatile("cp.async.wait_group %0;" :: "n"(2));
        __syncthreads();
        if (s + 3 < NSTAGE) issue(s + 3);
        else asm volatile("cp.async.commit_group;");

        const int buf = s & 3;
        const uint32_t sA = sbase + buf * STAGE_BYTES;
        const uint32_t sB = sA + STAGE_A_BYTES;

#pragma unroll
        for (int kc = 0; kc < 2; kc++) {
            uint32_t a[4][4], b[4][2];
#pragma unroll
            for (int mt = 0; mt < 4; mt++)
                ldmA(a[mt], sA + (aRow + mt * 16) * 64 + (((2 * kc + aKsel) ^ aSw) << 4));
#pragma unroll
            for (int nt = 0; nt < 4; nt++)
                ldmB(b[nt], sB + (bRow + nt * 8) * 64 + (((2 * kc + bKsel) ^ bSw) << 4));
#pragma unroll
            for (int mt = 0; mt < 4; mt++)
#pragma unroll
                for (int nt = 0; nt < 4; nt++)
                    mma16816(acc[mt][nt], a[mt][0], a[mt][1], a[mt][2], a[mt][3],
                             b[nt][0], b[nt][1]);
        }
    }

#pragma unroll
    for (int mt = 0; mt < 4; mt++) {
        int row = m0 + wm * 64 + mt * 16 + grp;
#pragma unroll
        for (int nt = 0; nt < 4; nt++) {
            int col = n0 + wn * 32 + nt * 8 + 2 * kq;
            if (col < Ntot) {
                float bv0 = 0.f, bv1 = 0.f;
                if (TANH) { bv0 = bias[col]; bv1 = bias[col + 1]; }
                float2 v0, v1;
                v0.x = acc[mt][nt][0]; v0.y = acc[mt][nt][1];
                v1.x = acc[mt][nt][2]; v1.y = acc[mt][nt][3];
                if (TANH) {
                    v0.x = fast_tanh(v0.x + bv0); v0.y = fast_tanh(v0.y + bv1);
                    v1.x = fast_tanh(v1.x + bv0); v1.y = fast_tanh(v1.y + bv1);
                }
                *(float2*)(C + (size_t)row * ldC + col)       = v0;
                *(float2*)(C + (size_t)(row + 8) * ldC + col) = v1;
            }
        }
    }
}

// ---------------- GRU combine (coalesced, no gather) ----------------
__global__ __launch_bounds__(HID) void gru_comb(
    const float* __restrict__ gi, const float* __restrict__ gh,
    const float* __restrict__ b_hh, const float* __restrict__ h0,
    float* __restrict__ h1, __half* __restrict__ h1h)
{
    const int b = blockIdx.x;
    const int h = threadIdx.x;
    const float* gib = gi + (size_t)b * G3H;
    const float* ghb = gh + (size_t)b * G3H;

    float gh_r = ghb[h]           + b_hh[h];
    float gh_z = ghb[h + HID]     + b_hh[h + HID];
    float gh_n = ghb[h + 2 * HID] + b_hh[h + 2 * HID];

    float r = 1.0f / (1.0f + __expf(-(gib[h] + gh_r)));
    float z = 1.0f / (1.0f + __expf(-(gib[h + HID] + gh_z)));
    float n = fast_tanh(gib[h + 2 * HID] + r * gh_n);
    float hp = h0[(size_t)b * HID + h];
    float hv = (1.0f - z) * n + z * hp;
    h1[(size_t)b * HID + h]  = hv;
    h1h[(size_t)b * HID + h] = __float2half(hv);
}

extern "C" void kernel_launch(void* const* d_in, const int* in_sizes, int n_in,
                              void* d_out, int out_size)
{
    const int*   ids    = (const int*)  d_in[0];
    const float* hidden = (const float*)d_in[1];
    const float* w_ih   = (const float*)d_in[2];
    const float* w_hh   = (const float*)d_in[3];
    const float* b_ih   = (const float*)d_in[4];
    const float* b_hh   = (const float*)d_in[5];
    const float* w_out  = (const float*)d_in[6];
    const float* b_out  = (const float*)d_in[7];

    float* out = (float*)d_out;
    float* h1  = out + ((size_t)out_size - (size_t)BATCH * HID);

    float* gh;   cudaGetSymbolAddress((void**)&gh,  g_gh);
    float* gi;   cudaGetSymbolAddress((void**)&gi,  g_gi);
    __half* woh; cudaGetSymbolAddress((void**)&woh, g_woh);
    __half* whh; cudaGetSymbolAddress((void**)&whh, g_whh);
    __half* hih; cudaGetSymbolAddress((void**)&hih, g_hidh);
    __half* h1h; cudaGetSymbolAddress((void**)&h1h, g_h1h);

    static cudaStream_t sA = nullptr, sB = nullptr;
    static cudaEvent_t ev0 = nullptr, evA = nullptr, evB = nullptr;
    if (!sA) {
        cudaFuncSetAttribute(gemm16<false>, cudaFuncAttributeMaxDynamicSharedMemorySize, SMEM_BYTES);
        cudaFuncSetAttribute(gemm16<true>,  cudaFuncAttributeMaxDynamicSharedMemorySize, SMEM_BYTES);
        cudaStreamCreateWithFlags(&sA, cudaStreamNonBlocking);
        cudaStreamCreateWithFlags(&sB, cudaStreamNonBlocking);
        cudaEventCreateWithFlags(&ev0, cudaEventDisableTiming);
        cudaEventCreateWithFlags(&evA, cudaEventDisableTiming);
        cudaEventCreateWithFlags(&evB, cudaEventDisableTiming);
    }

    // fork point
    cudaEventRecord(ev0, (cudaStream_t)0);
    cudaStreamWaitEvent(sA, ev0, 0);
    cudaStreamWaitEvent(sB, ev0, 0);

    // stream A: w_out f32 -> f16 (overlaps everything pre-K3)
    {
        int n4 = (VOCAB * HID) / 4;
        convk<<<(n4 + 255) / 256, 256, 0, sA>>>((const float4*)w_out, (__half2*)woh, n4);
    }
    cudaEventRecord(evA, sA);

    // stream B: w_ih gather (one load/thread, 393k threads)
    gather_gi<<<dim3(3, BATCH), 256, 0, sB>>>(ids, w_ih, b_ih, gi);
    cudaEventRecord(evB, sB);

    // main: small convs -> K1 -> (join gather) -> combine
    {
        int n1 = (G3H * HID) / 4, n2 = (BATCH * HID) / 4;
        convall<<<(n1 + n2 + 255) / 256, 256>>>(
            (const float4*)w_hh, (__half2*)whh, n1,
            (const float4*)hidden, (__half2*)hih, n2);
    }
    gemm16<false><<<dim3(BATCH / TM, G3H / TN), 256, SMEM_BYTES>>>(
        hih, whh, nullptr, gh, G3H, G3H);

    cudaStreamWaitEvent((cudaStream_t)0, evB, 0);
    gru_comb<<<BATCH, HID>>>(gi, gh, b_hh, hidden, h1, h1h);

    // join w_out conversion, then big GEMM
    cudaStreamWaitEvent((cudaStream_t)0, evA, 0);
    gemm16<true><<<dim3(BATCH / TM, (VOCAB + TN - 1) / TN), 256, SMEM_BYTES>>>(
        h1h, woh, b_out, out, VOCAB, VOCAB);
}

// round 7
// speedup vs baseline: 1.8427x; 1.0014x over previous
#include <cuda_runtime.h>
#include <cuda_fp16.h>
#include <cstdint>
#include <math.h>

#define VOCAB 50000
#define HID   256
#define BATCH 512
#define G3H   768
#define KDIM  256
#define BK    32
#define NSTAGE (KDIM / BK)     // 8
#define TM    128
#define TN    64
#define STAGE_A_BYTES (TM * 64)          // 8 KB
#define STAGE_B_BYTES (TN * 64)          // 4 KB
#define STAGE_BYTES   (STAGE_A_BYTES + STAGE_B_BYTES)   // 12 KB
#define SMEM_BYTES    (4 * STAGE_BYTES)                 // 48 KB

// scratch (static device globals -- allocation-free)
__device__ float  g_gh[BATCH * G3H];
__device__ float  g_gi[BATCH * G3H];
__device__ __half g_woh[(size_t)VOCAB * HID];
__device__ __half g_whh[G3H * HID];
__device__ __half g_hidh[BATCH * HID];
__device__ __half g_h1h[BATCH * HID];

// ---------------- helpers ----------------
__device__ __forceinline__ uint32_t smem_u32(const void* p) {
    uint32_t a;
    asm("{ .reg .u64 t; cvta.to.shared.u64 t, %1; cvt.u32.u64 %0, t; }" : "=r"(a) : "l"(p));
    return a;
}
__device__ __forceinline__ void cp16(uint32_t d, const void* g) {
    asm volatile("cp.async.cg.shared.global [%0], [%1], 16;" :: "r"(d), "l"(g));
}
__device__ __forceinline__ void ldm4(uint32_t a[4], uint32_t addr) {
    asm volatile("ldmatrix.sync.aligned.m8n8.x4.shared.b16 {%0,%1,%2,%3}, [%4];"
                 : "=r"(a[0]), "=r"(a[1]), "=r"(a[2]), "=r"(a[3]) : "r"(addr));
}
__device__ __forceinline__ void mma16816(float c[4], unsigned a0, unsigned a1,
                                         unsigned a2, unsigned a3,
                                         unsigned b0, unsigned b1) {
    asm volatile(
        "mma.sync.aligned.m16n8k16.row.col.f32.f16.f16.f32 "
        "{%0,%1,%2,%3}, {%4,%5,%6,%7}, {%8,%9}, {%0,%1,%2,%3};\n"
        : "+f"(c[0]), "+f"(c[1]), "+f"(c[2]), "+f"(c[3])
        : "r"(a0), "r"(a1), "r"(a2), "r"(a3), "r"(b0), "r"(b1));
}
__device__ __forceinline__ float fast_tanh(float x) {
    x = fminf(fmaxf(x, -15.f), 15.f);
    float e = __expf(2.f * x);
    return __fdividef(e - 1.f, e + 1.f);
}

// ---------------- conversions ----------------
__global__ __launch_bounds__(256) void convk(const float4* __restrict__ s,
                                             __half2* __restrict__ d, int n4) {
    int i = blockIdx.x * 256 + threadIdx.x;
    if (i < n4) {
        float4 v = s[i];
        d[2 * i]     = __floats2half2_rn(v.x, v.y);
        d[2 * i + 1] = __floats2half2_rn(v.z, v.w);
    }
}
__global__ __launch_bounds__(256) void convall(
    const float4* __restrict__ s1, __half2* __restrict__ d1, int n1,
    const float4* __restrict__ s2, __half2* __restrict__ d2, int n2)
{
    int i = blockIdx.x * 256 + threadIdx.x;
    if (i < n1) {
        float4 v = s1[i];
        d1[2 * i]     = __floats2half2_rn(v.x, v.y);
        d1[2 * i + 1] = __floats2half2_rn(v.z, v.w);
    } else {
        int j = i - n1;
        if (j < n2) {
            float4 v = s2[j];
            d2[2 * j]     = __floats2half2_rn(v.x, v.y);
            d2[2 * j + 1] = __floats2half2_rn(v.z, v.w);
        }
    }
}

// ---------------- w_ih gather ----------------
__global__ __launch_bounds__(256) void gather_gi(
    const int* __restrict__ ids, const float* __restrict__ w_ih,
    const float* __restrict__ b_ih, float* __restrict__ gi)
{
    const int h = blockIdx.x * 256 + threadIdx.x;
    const int b = blockIdx.y;
    const int idx = __ldg(&ids[b]);
    gi[b * G3H + h] = __ldg(&w_ih[(size_t)h * VOCAB + idx]) + b_ih[h];
}

// ---------------- fp16 GEMM: CTA 128x64, warp tile 32x32, 3+ CTAs/SM ----------
// C[m,n] = [tanh](sum_k A[m,k]*B[n,k] [+ bias[n]])
// A: [M,256] f16, M % 128 == 0.  B: [Ntot,256] f16, rows clamped.
// 256 threads = 8 warps (4m x 2n), mma m16n8k16.
template <bool TANH>
__global__ __launch_bounds__(256, 3) void gemm16(
    const __half* __restrict__ A, const __half* __restrict__ B,
    const float* __restrict__ bias, float* __restrict__ C,
    int Ntot, int ldC)
{
    extern __shared__ char smem[];
    const int tid  = threadIdx.x;
    const int lane = tid & 31;
    const int warp = tid >> 5;
    const int wm   = warp & 3;       // 0..3 -> 32-row slab
    const int wn   = warp >> 2;      // 0..1 -> 32-col slab
    const int grp  = lane >> 2;
    const int kq   = lane & 3;
    const int m0   = blockIdx.x * TM;
    const int n0   = blockIdx.y * TN;
    const uint32_t sbase = smem_u32(smem);

    // cp.async mapping: rows of 64B = 4 chunks of 16B
    const int rcp = tid >> 2;        // 0..63
    const int cc  = tid & 3;

    // ldmatrix lane addressing
    const int aRow = wm * 32 + (lane & 15);      // + mt*16
    const int aSw  = ((lane & 15) >> 1) & 3;
    const int aK   = lane >> 4;                  // k-half select
    const int bRow = wn * 32 + ((lane >> 4) << 3) + (lane & 7);  // + p*16
    const int bSw  = ((lane & 7) >> 1) & 3;
    const int bK   = (lane >> 3) & 1;

    float acc[2][4][4];
#pragma unroll
    for (int mt = 0; mt < 2; mt++)
#pragma unroll
        for (int nt = 0; nt < 4; nt++)
#pragma unroll
            for (int i = 0; i < 4; i++) acc[mt][nt][i] = 0.f;

    auto issue = [&](int s) {
        const int buf = s & 3;
        const uint32_t sA = sbase + buf * STAGE_BYTES;
        const uint32_t sB = sA + STAGE_A_BYTES;
        const int k0 = s * BK;
        const int sw = ((cc ^ ((rcp >> 1) & 3)) << 4);
#pragma unroll
        for (int i = 0; i < 2; i++) {          // A: 128 rows
            int r = rcp + i * 64;
            int swr = ((cc ^ ((r >> 1) & 3)) << 4);
            cp16(sA + r * 64 + swr, A + (size_t)(m0 + r) * KDIM + k0 + cc * 8);
        }
        {                                      // B: 64 rows
            int rb = n0 + rcp;
            if (rb > Ntot - 1) rb = Ntot - 1;
            cp16(sB + rcp * 64 + sw, B + (size_t)rb * KDIM + k0 + cc * 8);
        }
        asm volatile("cp.async.commit_group;");
    };

    issue(0); issue(1); issue(2);

    for (int s = 0; s < NSTAGE; s++) {
        asm volatile("cp.async.wait_group %0;" :: "n"(2));
        __syncthreads();
        if (s + 3 < NSTAGE) issue(s + 3);
        else asm volatile("cp.async.commit_group;");

        const int buf = s & 3;
        const uint32_t sA = sbase + buf * STAGE_BYTES;
        const uint32_t sB = sA + STAGE_A_BYTES;

#pragma unroll
        for (int kc = 0; kc < 2; kc++) {
            uint32_t a[2][4], b[4][2];
#pragma unroll
            for (int mt = 0; mt < 2; mt++)
                ldm4(a[mt], sA + (aRow + mt * 16) * 64 + (((2 * kc + aK) ^ aSw) << 4));
#pragma unroll
            for (int p = 0; p < 2; p++) {
                uint32_t r4[4];
                ldm4(r4, sB + (bRow + p * 16) * 64 + (((2 * kc + bK) ^ bSw) << 4));
                b[2 * p][0]     = r4[0]; b[2 * p][1]     = r4[1];
                b[2 * p + 1][0] = r4[2]; b[2 * p + 1][1] = r4[3];
            }
#pragma unroll
            for (int mt = 0; mt < 2; mt++)
#pragma unroll
                for (int nt = 0; nt < 4; nt++)
                    mma16816(acc[mt][nt], a[mt][0], a[mt][1], a[mt][2], a[mt][3],
                             b[nt][0], b[nt][1]);
        }
    }

    // epilogue
#pragma unroll
    for (int mt = 0; mt < 2; mt++) {
        int row = m0 + wm * 32 + mt * 16 + grp;
#pragma unroll
        for (int nt = 0; nt < 4; nt++) {
            int col = n0 + wn * 32 + nt * 8 + 2 * kq;
            if (col < Ntot) {
                float bv0 = 0.f, bv1 = 0.f;
                if (TANH) { bv0 = bias[col]; bv1 = bias[col + 1]; }
                float2 v0, v1;
                v0.x = acc[mt][nt][0]; v0.y = acc[mt][nt][1];
                v1.x = acc[mt][nt][2]; v1.y = acc[mt][nt][3];
                if (TANH) {
                    v0.x = fast_tanh(v0.x + bv0); v0.y = fast_tanh(v0.y + bv1);
                    v1.x = fast_tanh(v1.x + bv0); v1.y = fast_tanh(v1.y + bv1);
                }
                *(float2*)(C + (size_t)row * ldC + col)       = v0;
                *(float2*)(C + (size_t)(row + 8) * ldC + col) = v1;
            }
        }
    }
}

// ---------------- GRU combine ----------------
__global__ __launch_bounds__(HID) void gru_comb(
    const float* __restrict__ gi, const float* __restrict__ gh,
    const float* __restrict__ b_hh, const float* __restrict__ h0,
    float* __restrict__ h1, __half* __restrict__ h1h)
{
    const int b = blockIdx.x;
    const int h = threadIdx.x;
    const float* gib = gi + (size_t)b * G3H;
    const float* ghb = gh + (size_t)b * G3H;

    float gh_r = ghb[h]           + b_hh[h];
    float gh_z = ghb[h + HID]     + b_hh[h + HID];
    float gh_n = ghb[h + 2 * HID] + b_hh[h + 2 * HID];

    float r = 1.0f / (1.0f + __expf(-(gib[h] + gh_r)));
    float z = 1.0f / (1.0f + __expf(-(gib[h + HID] + gh_z)));
    float n = fast_tanh(gib[h + 2 * HID] + r * gh_n);
    float hp = h0[(size_t)b * HID + h];
    float hv = (1.0f - z) * n + z * hp;
    h1[(size_t)b * HID + h]  = hv;
    h1h[(size_t)b * HID + h] = __float2half(hv);
}

extern "C" void kernel_launch(void* const* d_in, const int* in_sizes, int n_in,
                              void* d_out, int out_size)
{
    const int*   ids    = (const int*)  d_in[0];
    const float* hidden = (const float*)d_in[1];
    const float* w_ih   = (const float*)d_in[2];
    const float* w_hh   = (const float*)d_in[3];
    const float* b_ih   = (const float*)d_in[4];
    const float* b_hh   = (const float*)d_in[5];
    const float* w_out  = (const float*)d_in[6];
    const float* b_out  = (const float*)d_in[7];

    float* out = (float*)d_out;
    float* h1  = out + ((size_t)out_size - (size_t)BATCH * HID);

    float* gh;   cudaGetSymbolAddress((void**)&gh,  g_gh);
    float* gi;   cudaGetSymbolAddress((void**)&gi,  g_gi);
    __half* woh; cudaGetSymbolAddress((void**)&woh, g_woh);
    __half* whh; cudaGetSymbolAddress((void**)&whh, g_whh);
    __half* hih; cudaGetSymbolAddress((void**)&hih, g_hidh);
    __half* h1h; cudaGetSymbolAddress((void**)&h1h, g_h1h);

    static cudaStream_t sA = nullptr, sB = nullptr;
    static cudaEvent_t ev0 = nullptr, evA = nullptr, evB = nullptr;
    if (!sA) {
        cudaFuncSetAttribute(gemm16<false>, cudaFuncAttributeMaxDynamicSharedMemorySize, SMEM_BYTES);
        cudaFuncSetAttribute(gemm16<true>,  cudaFuncAttributeMaxDynamicSharedMemorySize, SMEM_BYTES);
        cudaStreamCreateWithFlags(&sA, cudaStreamNonBlocking);
        cudaStreamCreateWithFlags(&sB, cudaStreamNonBlocking);
        cudaEventCreateWithFlags(&ev0, cudaEventDisableTiming);
        cudaEventCreateWithFlags(&evA, cudaEventDisableTiming);
        cudaEventCreateWithFlags(&evB, cudaEventDisableTiming);
    }

    // fork point
    cudaEventRecord(ev0, (cudaStream_t)0);
    cudaStreamWaitEvent(sA, ev0, 0);
    cudaStreamWaitEvent(sB, ev0, 0);

    // stream A: w_out f32 -> f16
    {
        int n4 = (VOCAB * HID) / 4;
        convk<<<(n4 + 255) / 256, 256, 0, sA>>>((const float4*)w_out, (__half2*)woh, n4);
    }
    cudaEventRecord(evA, sA);

    // stream B: w_ih gather
    gather_gi<<<dim3(3, BATCH), 256, 0, sB>>>(ids, w_ih, b_ih, gi);
    cudaEventRecord(evB, sB);

    // main: small convs -> K1 -> combine
    {
        int n1 = (G3H * HID) / 4, n2 = (BATCH * HID) / 4;
        convall<<<(n1 + n2 + 255) / 256, 256>>>(
            (const float4*)w_hh, (__half2*)whh, n1,
            (const float4*)hidden, (__half2*)hih, n2);
    }
    gemm16<false><<<dim3(BATCH / TM, G3H / TN), 256, SMEM_BYTES>>>(
        hih, whh, nullptr, gh, G3H, G3H);

    cudaStreamWaitEvent((cudaStream_t)0, evB, 0);
    gru_comb<<<BATCH, HID>>>(gi, gh, b_hh, hidden, h1, h1h);

    cudaStreamWaitEvent((cudaStream_t)0, evA, 0);
    gemm16<true><<<dim3(BATCH / TM, (VOCAB + TN - 1) / TN), 256, SMEM_BYTES>>>(
        h1h, woh, b_out, out, VOCAB, VOCAB);
}